// round 6
// baseline (speedup 1.0000x reference)
#include <cuda_runtime.h>
#include <math.h>

#define SS 512
#define NN 64
#define CC 512
#define QQ 256
#define VV 10
#define GG 2048
#define NB5 128
#define HTS 68     // hts stride (words), mult of 4
#define WTS 20     // wts stride
#define RSTR 516   // reduction stride

__device__ float g_a0[SS * NN];
__device__ float g_a1[SS * NN];
__device__ float g_A[(size_t)NN * SS * QQ];
__device__ float g_queue[(size_t)QQ * NN * CC];
__device__ float g_xg[(size_t)QQ * NN * GG];
__device__ float g_ght[2 * CC * NN];              // h transposed [buf][k][n]
__device__ float g_hs[(size_t)QQ * NN * CC];
__device__ unsigned g_barcnt;

// ---------------- K1: action softmax ----------------
__global__ void k1_actions(const float* __restrict__ memory,
                           const float* __restrict__ W_act,
                           const float* __restrict__ b_act) {
    int warp = blockIdx.x * (blockDim.x >> 5) + (threadIdx.x >> 5);
    int lane = threadIdx.x & 31;
    if (warp >= SS * NN) return;
    const float* row = memory + (size_t)warp * CC;
    float z0 = 0.f, z1 = 0.f;
    for (int c = lane; c < CC; c += 32) {
        float m = row[c];
        z0 += m * W_act[2 * c];
        z1 += m * W_act[2 * c + 1];
    }
#pragma unroll
    for (int o = 16; o; o >>= 1) {
        z0 += __shfl_down_sync(0xffffffffu, z0, o);
        z1 += __shfl_down_sync(0xffffffffu, z1, o);
    }
    if (lane == 0) {
        z0 += b_act[0]; z1 += b_act[1];
        float mx = fmaxf(z0, z1);
        float e0 = expf(z0 - mx), e1 = expf(z1 - mx);
        float inv = 1.f / (e0 + e1);
        g_a0[warp] = e0 * inv;
        g_a1[warp] = e1 * inv;
    }
}

// ---------------- K2: posvec recurrence ----------------
__global__ void k2_posvec() {
    if (blockIdx.x == 0 && threadIdx.x == 0) g_barcnt = 0u;
    int n = blockIdx.x;
    int q = threadIdx.x;
    __shared__ float sp[QQ];
    __shared__ float sa0[SS], sa1[SS];
    for (int s = q; s < SS; s += QQ) {
        sa0[s] = g_a0[s * NN + n];
        sa1[s] = g_a1[s * NN + n];
    }
    __syncthreads();
    float p = (q == 0) ? 1.f : 0.f;
    float* An = g_A + (size_t)n * SS * QQ;
    for (int s = 0; s < SS; s++) {
        float a0 = sa0[s], a1 = sa1[s];
        An[(size_t)s * QQ + q] = p * a1;
        sp[q] = p;
        __syncthreads();
        float prev = sp[(q + QQ - 1) & (QQ - 1)];
        __syncthreads();
        p = p * a0 + prev * a1;
    }
}

// ---------------- fp32 tile helper (k3) ----------------
__device__ __forceinline__ void fma_8x4(float acc[32], const float* __restrict__ As,
                                        const float* __restrict__ Bs, int ty, int tx) {
#pragma unroll
    for (int k = 0; k < 16; k++) {
        float4 A0 = *(const float4*)&As[k * 128 + ty * 8];
        float4 A1 = *(const float4*)&As[k * 128 + ty * 8 + 4];
        float4 B0 = *(const float4*)&Bs[k * 64 + tx * 4];
        float a[8] = {A0.x, A0.y, A0.z, A0.w, A1.x, A1.y, A1.z, A1.w};
        float b[4] = {B0.x, B0.y, B0.z, B0.w};
#pragma unroll
        for (int i = 0; i < 8; i++)
#pragma unroll
            for (int j = 0; j < 4; j++) acc[i * 4 + j] = fmaf(a[i], b[j], acc[i * 4 + j]);
    }
}

// ---------------- K3: queue ----------------
__global__ void k3_queue(const float* __restrict__ memory) {
    __shared__ __align__(16) float As[16 * 128];
    __shared__ __align__(16) float Bs[16 * 64];
    int n = blockIdx.z;
    int q0 = blockIdx.y * 128;
    int c0 = blockIdx.x * 64;
    int tid = threadIdx.x;
    int ty = tid >> 4, tx = tid & 15;
    float acc[32];
#pragma unroll
    for (int i = 0; i < 32; i++) acc[i] = 0.f;
    const float* Abase = g_A + (size_t)n * SS * QQ + q0;
    const float* Bbase = memory + (size_t)n * CC + c0;
    for (int s0 = 0; s0 < SS; s0 += 16) {
#pragma unroll
        for (int l = 0; l < 2; l++) {
            int f = tid + l * 256;
            int row = f >> 5, col4 = f & 31;
            *(float4*)&As[row * 128 + col4 * 4] =
                *(const float4*)&Abase[(size_t)(s0 + row) * QQ + col4 * 4];
        }
        {
            int rb = tid >> 4, cb = tid & 15;
            *(float4*)&Bs[rb * 64 + cb * 4] =
                *(const float4*)&Bbase[(size_t)(s0 + rb) * NN * CC + cb * 4];
        }
        __syncthreads();
        fma_8x4(acc, As, Bs, ty, tx);
        __syncthreads();
    }
#pragma unroll
    for (int i = 0; i < 8; i++) {
        int q = q0 + ty * 8 + i;
        float4 v = make_float4(acc[i * 4], acc[i * 4 + 1], acc[i * 4 + 2], acc[i * 4 + 3]);
        *(float4*)&g_queue[((size_t)q * NN + n) * CC + c0 + tx * 4] = v;
    }
}

// ---------------- K4: xg = queue @ W_ih^T via tf32 mma.sync ----------------
__device__ __forceinline__ float to_tf32(float x) {
    unsigned r;
    asm("cvt.rna.tf32.f32 %0, %1;" : "=r"(r) : "f"(x));
    return __uint_as_float(r);
}
__device__ __forceinline__ void mma_tf32(float& d0, float& d1, float& d2, float& d3,
                                         float a0, float a1, float a2, float a3,
                                         float b0, float b1) {
    asm volatile(
        "mma.sync.aligned.m16n8k8.row.col.f32.tf32.tf32.f32 "
        "{%0,%1,%2,%3},{%4,%5,%6,%7},{%8,%9},{%0,%1,%2,%3};"
        : "+f"(d0), "+f"(d1), "+f"(d2), "+f"(d3)
        : "r"(__float_as_uint(a0)), "r"(__float_as_uint(a1)),
          "r"(__float_as_uint(a2)), "r"(__float_as_uint(a3)),
          "r"(__float_as_uint(b0)), "r"(__float_as_uint(b1)));
}

__global__ void __launch_bounds__(256) k4_xgates(const float* __restrict__ W_ih,
                                                 const float* __restrict__ b_ih,
                                                 const float* __restrict__ b_hh) {
    __shared__ __align__(16) float As[128 * 20];
    __shared__ __align__(16) float Bs[128 * 20];
    int tid = threadIdx.x;
    int m0 = blockIdx.y * 128, g0 = blockIdx.x * 128;
    int warp = tid >> 5, lane = tid & 31;
    int wm = warp >> 1, wn = warp & 1;   // 4x2 warps; warp tile 32x64
    int lr = lane >> 2, lc = lane & 3;

    float c[2][8][4];
#pragma unroll
    for (int a = 0; a < 2; a++)
#pragma unroll
        for (int b = 0; b < 8; b++)
#pragma unroll
            for (int d = 0; d < 4; d++) c[a][b][d] = 0.f;

    int sr = tid >> 2;
    int sk = (tid & 3) * 4;
    const float* Ag = g_queue + (size_t)(m0 + sr) * CC + sk;
    const float* Bg = W_ih + (size_t)(g0 + sr) * CC + sk;

    float4 ra0 = *(const float4*)Ag;
    float4 ra1 = *(const float4*)(Ag + (size_t)64 * CC);
    float4 rb0 = *(const float4*)Bg;
    float4 rb1 = *(const float4*)(Bg + (size_t)64 * CC);

    for (int kt = 0; kt < 32; kt++) {
        *(float4*)&As[sr * 20 + sk] =
            make_float4(to_tf32(ra0.x), to_tf32(ra0.y), to_tf32(ra0.z), to_tf32(ra0.w));
        *(float4*)&As[(sr + 64) * 20 + sk] =
            make_float4(to_tf32(ra1.x), to_tf32(ra1.y), to_tf32(ra1.z), to_tf32(ra1.w));
        *(float4*)&Bs[sr * 20 + sk] =
            make_float4(to_tf32(rb0.x), to_tf32(rb0.y), to_tf32(rb0.z), to_tf32(rb0.w));
        *(float4*)&Bs[(sr + 64) * 20 + sk] =
            make_float4(to_tf32(rb1.x), to_tf32(rb1.y), to_tf32(rb1.z), to_tf32(rb1.w));
        __syncthreads();
        if (kt < 31) {
            int off = (kt + 1) * 16;
            ra0 = *(const float4*)(Ag + off);
            ra1 = *(const float4*)(Ag + (size_t)64 * CC + off);
            rb0 = *(const float4*)(Bg + off);
            rb1 = *(const float4*)(Bg + (size_t)64 * CC + off);
        }
#pragma unroll
        for (int s = 0; s < 2; s++) {
            int k0 = s * 8;
            float a[2][4];
#pragma unroll
            for (int tm = 0; tm < 2; tm++) {
                int row = wm * 32 + tm * 16 + lr;
                a[tm][0] = As[row * 20 + k0 + lc];
                a[tm][1] = As[(row + 8) * 20 + k0 + lc];
                a[tm][2] = As[row * 20 + k0 + lc + 4];
                a[tm][3] = As[(row + 8) * 20 + k0 + lc + 4];
            }
#pragma unroll
            for (int tn = 0; tn < 8; tn++) {
                int col = wn * 64 + tn * 8 + lr;
                float b0 = Bs[col * 20 + k0 + lc];
                float b1 = Bs[col * 20 + k0 + lc + 4];
#pragma unroll
                for (int tm = 0; tm < 2; tm++)
                    mma_tf32(c[tm][tn][0], c[tm][tn][1], c[tm][tn][2], c[tm][tn][3],
                             a[tm][0], a[tm][1], a[tm][2], a[tm][3], b0, b1);
            }
        }
        __syncthreads();
    }
    // epilogue
#pragma unroll
    for (int tm = 0; tm < 2; tm++) {
#pragma unroll
        for (int tn = 0; tn < 8; tn++) {
            int g = g0 + wn * 64 + tn * 8 + lc * 2;
            float bv0 = b_ih[g] + b_hh[g];
            float bv1 = b_ih[g + 1] + b_hh[g + 1];
            int r0 = m0 + wm * 32 + tm * 16 + lr;
            float2 v0 = make_float2(c[tm][tn][0] + bv0, c[tm][tn][1] + bv1);
            float2 v1 = make_float2(c[tm][tn][2] + bv0, c[tm][tn][3] + bv1);
            *(float2*)&g_xg[(size_t)r0 * GG + g] = v0;
            *(float2*)&g_xg[(size_t)(r0 + 8) * GG + g] = v1;
        }
    }
}

// ---------------- K5: persistent LSTM ----------------
__device__ __forceinline__ float sigf(float x) { return 1.f / (1.f + expf(-x)); }

__device__ __forceinline__ void gridbar(unsigned target) {
    if (threadIdx.x == 0) {
        __threadfence();
        atomicAdd(&g_barcnt, 1u);
        while (*(volatile unsigned*)&g_barcnt < target) __nanosleep(32);
        __threadfence();
    }
    __syncthreads();
}

__global__ void __launch_bounds__(256, 1) k5_lstm(const float* __restrict__ W_hh) {
    extern __shared__ float sm[];
    float* hts = sm;                       // [512][HTS]
    float* wts = sm + CC * HTS;            // [512][WTS]
    float* red = wts + CC * WTS;           // [16][RSTR]
    float* gsm = red + 16 * RSTR;          // [16][64]
    int tid = threadIdx.x;
    int b = blockIdx.x;
    int c0 = b * 4;
    int ks = tid >> 4, pos = tid & 15;
    int nt = pos >> 1, gt = pos & 1;

    // preload transposed W slice: wts[k][gi], gi = gate*4 + j
    {
        int gi = tid >> 4;
        int gate = gi >> 2, j = gi & 3;
        const float* wrow = W_hh + (size_t)(gate * CC + c0 + j) * CC;
        int kc = (tid & 15) * 32;
#pragma unroll
        for (int u = 0; u < 8; u++) {
            float4 v = *(const float4*)&wrow[kc + u * 4];
            wts[(kc + u * 4 + 0) * WTS + gi] = v.x;
            wts[(kc + u * 4 + 1) * WTS + gi] = v.y;
            wts[(kc + u * 4 + 2) * WTS + gi] = v.z;
            wts[(kc + u * 4 + 3) * WTS + gi] = v.w;
        }
    }
    if (tid < 64) {
#pragma unroll
        for (int j = 0; j < 4; j++) g_ght[(c0 + j) * NN + tid] = 0.f;
    }
    __syncthreads();
    unsigned u = 1;
    gridbar(u * NB5); u++;

    float creg[4] = {0.f, 0.f, 0.f, 0.f};

    for (int step = 0; step < QQ; step++) {
        int par = step & 1;
        // prefetch this step's input gates (used in activation)
        float xvf[4][4];
        if (tid < 64) {
            const float* xb = g_xg + ((size_t)step * NN + tid) * GG + c0;
#pragma unroll
            for (int g = 0; g < 4; g++) {
                float4 v = *(const float4*)&xb[g * 512];
                xvf[g][0] = v.x; xvf[g][1] = v.y; xvf[g][2] = v.z; xvf[g][3] = v.w;
            }
        }
        // stage h (transposed in global) into smem
        const float* hb = g_ght + par * (CC * NN);
#pragma unroll
        for (int it = 0; it < 32; it++) {
            int f = tid + it * 256;         // float4 slot, 0..8191
            int k = f >> 4;
            int n4 = (f & 15) * 4;
            float4 v = __ldcg((const float4*)&hb[k * NN + n4]);
            *(float4*)&hts[k * HTS + n4] = v;
        }
        __syncthreads();

        // 8x8 register-tile GEMM, K-split 16
        float acc[8][8];
#pragma unroll
        for (int i = 0; i < 8; i++)
#pragma unroll
            for (int j = 0; j < 8; j++) acc[i][j] = 0.f;
        int stag = (ks & 1) << 4;
        int hbase = nt * 8, wbase = gt * 8;
#pragma unroll 4
        for (int i = 0; i < 32; i++) {
            int kk = ks * 32 + ((i + stag) & 31);
            float4 h0 = *(const float4*)&hts[kk * HTS + hbase];
            float4 h1 = *(const float4*)&hts[kk * HTS + hbase + 4];
            float4 w0 = *(const float4*)&wts[kk * WTS + wbase];
            float4 w1 = *(const float4*)&wts[kk * WTS + wbase + 4];
            float hv[8] = {h0.x, h0.y, h0.z, h0.w, h1.x, h1.y, h1.z, h1.w};
            float wv[8] = {w0.x, w0.y, w0.z, w0.w, w1.x, w1.y, w1.z, w1.w};
#pragma unroll
            for (int ni = 0; ni < 8; ni++)
#pragma unroll
                for (int gj = 0; gj < 8; gj++)
                    acc[ni][gj] = fmaf(hv[ni], wv[gj], acc[ni][gj]);
        }
        // pair-reduce across ks parity via shuffle
#pragma unroll
        for (int ni = 0; ni < 8; ni++)
#pragma unroll
            for (int gj = 0; gj < 8; gj++)
                acc[ni][gj] += __shfl_xor_sync(0xffffffffu, acc[ni][gj], 16);
        int w = tid >> 5;   // ks-pair index
        if (((tid >> 4) & 1) == 0) {
            float* rp = &red[pos * RSTR + w * 64];
#pragma unroll
            for (int ni = 0; ni < 8; ni++) {
                *(float4*)&rp[ni * 8] =
                    make_float4(acc[ni][0], acc[ni][1], acc[ni][2], acc[ni][3]);
                *(float4*)&rp[ni * 8 + 4] =
                    make_float4(acc[ni][4], acc[ni][5], acc[ni][6], acc[ni][7]);
            }
        }
        __syncthreads();
        // final 8-way reduction -> gsm[gi][n]
        {
            int rp = tid & 15;
            int base = (tid >> 4) * 4;
#pragma unroll
            for (int e = 0; e < 4; e++) {
                int idx = base + e;
                float s = 0.f;
#pragma unroll
                for (int w2 = 0; w2 < 8; w2++) s += red[rp * RSTR + w2 * 64 + idx];
                int ni = idx >> 3, gj = idx & 7;
                int n = (rp >> 1) * 8 + ni;
                int gi = (rp & 1) * 8 + gj;
                gsm[gi * 64 + n] = s;
            }
        }
        __syncthreads();

        // activation + h/c update
        if (tid < 64) {
            int nxt = (step + 1) & 1;
            float* ho = g_ght + nxt * (CC * NN);
            float* hsout = g_hs + ((size_t)step * NN + tid) * CC + c0;
#pragma unroll
            for (int j = 0; j < 4; j++) {
                float iv = gsm[(0 * 4 + j) * 64 + tid] + xvf[0][j];
                float fv = gsm[(1 * 4 + j) * 64 + tid] + xvf[1][j];
                float gv = gsm[(2 * 4 + j) * 64 + tid] + xvf[2][j];
                float ov = gsm[(3 * 4 + j) * 64 + tid] + xvf[3][j];
                float cc = sigf(fv) * creg[j] + sigf(iv) * tanhf(gv);
                creg[j] = cc;
                float h = sigf(ov) * tanhf(cc);
                ho[(c0 + j) * NN + tid] = h;
                hsout[j] = h;
            }
        }
        __syncthreads();
        gridbar(u * NB5); u++;
    }
}

// ---------------- K6: LayerNorm + decode ----------------
__global__ void k6_lndec(const float* __restrict__ gamma,
                         const float* __restrict__ beta,
                         const float* __restrict__ W_dec,
                         const float* __restrict__ b_dec,
                         float* __restrict__ out) {
    __shared__ float sW[CC * VV];
    __shared__ float sG[CC], sB[CC], sbd[VV];
    int tid = threadIdx.x;
    for (int i = tid; i < CC * VV; i += 256) sW[i] = W_dec[i];
    for (int i = tid; i < CC; i += 256) { sG[i] = gamma[i]; sB[i] = beta[i]; }
    if (tid < VV) sbd[tid] = b_dec[tid];
    __syncthreads();

    int warp = blockIdx.x * 8 + (tid >> 5);
    int lane = tid & 31;
    if (warp >= QQ * NN) return;
    const float* row = g_hs + (size_t)warp * CC;

    float x[16];
    float s = 0.f, s2 = 0.f;
#pragma unroll
    for (int t = 0; t < 4; t++) {
        float4 v = *(const float4*)&row[lane * 4 + t * 128];
        x[t * 4 + 0] = v.x; x[t * 4 + 1] = v.y; x[t * 4 + 2] = v.z; x[t * 4 + 3] = v.w;
        s += v.x + v.y + v.z + v.w;
        s2 += v.x * v.x + v.y * v.y + v.z * v.z + v.w * v.w;
    }
#pragma unroll
    for (int o = 16; o; o >>= 1) {
        s += __shfl_xor_sync(0xffffffffu, s, o);
        s2 += __shfl_xor_sync(0xffffffffu, s2, o);
    }
    float mu = s * (1.f / CC);
    float var = s2 * (1.f / CC) - mu * mu;
    float rs = rsqrtf(var + 1e-5f);

    float acc[VV];
#pragma unroll
    for (int v = 0; v < VV; v++) acc[v] = 0.f;
#pragma unroll
    for (int t = 0; t < 4; t++) {
#pragma unroll
        for (int e = 0; e < 4; e++) {
            int c = lane * 4 + t * 128 + e;
            float nv = (x[t * 4 + e] - mu) * rs * sG[c] + sB[c];
#pragma unroll
            for (int v = 0; v < VV; v++) acc[v] = fmaf(nv, sW[c * VV + v], acc[v]);
        }
    }
#pragma unroll
    for (int v = 0; v < VV; v++) {
        float a = acc[v];
#pragma unroll
        for (int o = 16; o; o >>= 1) a += __shfl_xor_sync(0xffffffffu, a, o);
        if (lane == 0) out[(size_t)warp * VV + v] = a + sbd[v];
    }
}

extern "C" void kernel_launch(void* const* d_in, const int* in_sizes, int n_in,
                              void* d_out, int out_size) {
    const float* memory = (const float*)d_in[0];
    const float* W_act  = (const float*)d_in[1];
    const float* b_act  = (const float*)d_in[2];
    const float* W_ih   = (const float*)d_in[3];
    const float* W_hh   = (const float*)d_in[4];
    const float* b_ih   = (const float*)d_in[5];
    const float* b_hh   = (const float*)d_in[6];
    const float* lng    = (const float*)d_in[7];
    const float* lnb    = (const float*)d_in[8];
    const float* W_dec  = (const float*)d_in[9];
    const float* b_dec  = (const float*)d_in[10];
    float* out = (float*)d_out;

    k1_actions<<<(SS * NN + 7) / 8, 256>>>(memory, W_act, b_act);
    k2_posvec<<<NN, QQ>>>();
    k3_queue<<<dim3(CC / 64, QQ / 128, NN), 256>>>(memory);
    k4_xgates<<<dim3(GG / 128, (QQ * NN) / 128), 256>>>(W_ih, b_ih, b_hh);

    int smem5 = (CC * HTS + CC * WTS + 16 * RSTR + 16 * 64) * sizeof(float);
    cudaFuncSetAttribute(k5_lstm, cudaFuncAttributeMaxDynamicSharedMemorySize, smem5);
    k5_lstm<<<NB5, 256, smem5>>>(W_hh);

    k6_lndec<<<(QQ * NN + 7) / 8, 256>>>(lng, lnb, W_dec, b_dec, out);
}

// round 7
// speedup vs baseline: 1.4015x; 1.4015x over previous
#include <cuda_runtime.h>
#include <math.h>

#define SS 512
#define NN 64
#define CC 512
#define QQ 256
#define VV 10
#define GG 2048
#define NB5 128
#define HTS2 516   // hts [n][k] stride
#define WTS2 24    // wts [k][gi] stride

__device__ float g_a0[SS * NN];
__device__ float g_a1[SS * NN];
__device__ float g_A[(size_t)NN * SS * QQ];
__device__ float g_queue[(size_t)QQ * NN * CC];
__device__ float g_xg[(size_t)QQ * NN * GG];
__device__ float g_gh[2 * NN * CC];               // h (tf32-rounded) [buf][n][k]
__device__ float g_hs[(size_t)QQ * NN * CC];
__device__ unsigned g_barcnt;

// ---------------- tf32 helpers ----------------
__device__ __forceinline__ float to_tf32(float x) {
    unsigned r;
    asm("cvt.rna.tf32.f32 %0, %1;" : "=r"(r) : "f"(x));
    return __uint_as_float(r);
}
__device__ __forceinline__ void mma_tf32(float& d0, float& d1, float& d2, float& d3,
                                         float a0, float a1, float a2, float a3,
                                         float b0, float b1) {
    asm volatile(
        "mma.sync.aligned.m16n8k8.row.col.f32.tf32.tf32.f32 "
        "{%0,%1,%2,%3},{%4,%5,%6,%7},{%8,%9},{%0,%1,%2,%3};"
        : "+f"(d0), "+f"(d1), "+f"(d2), "+f"(d3)
        : "r"(__float_as_uint(a0)), "r"(__float_as_uint(a1)),
          "r"(__float_as_uint(a2)), "r"(__float_as_uint(a3)),
          "r"(__float_as_uint(b0)), "r"(__float_as_uint(b1)));
}

// ---------------- K1: action softmax ----------------
__global__ void k1_actions(const float* __restrict__ memory,
                           const float* __restrict__ W_act,
                           const float* __restrict__ b_act) {
    int warp = blockIdx.x * (blockDim.x >> 5) + (threadIdx.x >> 5);
    int lane = threadIdx.x & 31;
    if (warp >= SS * NN) return;
    const float* row = memory + (size_t)warp * CC;
    float z0 = 0.f, z1 = 0.f;
    for (int c = lane; c < CC; c += 32) {
        float m = row[c];
        z0 += m * W_act[2 * c];
        z1 += m * W_act[2 * c + 1];
    }
#pragma unroll
    for (int o = 16; o; o >>= 1) {
        z0 += __shfl_down_sync(0xffffffffu, z0, o);
        z1 += __shfl_down_sync(0xffffffffu, z1, o);
    }
    if (lane == 0) {
        z0 += b_act[0]; z1 += b_act[1];
        float mx = fmaxf(z0, z1);
        float e0 = expf(z0 - mx), e1 = expf(z1 - mx);
        float inv = 1.f / (e0 + e1);
        g_a0[warp] = e0 * inv;
        g_a1[warp] = e1 * inv;
    }
}

// ---------------- K2: posvec recurrence ----------------
__global__ void k2_posvec() {
    if (blockIdx.x == 0 && threadIdx.x == 0) g_barcnt = 0u;
    int n = blockIdx.x;
    int q = threadIdx.x;
    __shared__ float sp[QQ];
    __shared__ float sa0[SS], sa1[SS];
    for (int s = q; s < SS; s += QQ) {
        sa0[s] = g_a0[s * NN + n];
        sa1[s] = g_a1[s * NN + n];
    }
    __syncthreads();
    float p = (q == 0) ? 1.f : 0.f;
    float* An = g_A + (size_t)n * SS * QQ;
    for (int s = 0; s < SS; s++) {
        float a0 = sa0[s], a1 = sa1[s];
        An[(size_t)s * QQ + q] = p * a1;
        sp[q] = p;
        __syncthreads();
        float prev = sp[(q + QQ - 1) & (QQ - 1)];
        __syncthreads();
        p = p * a0 + prev * a1;
    }
}

// ---------------- fp32 tile helper (k3) ----------------
__device__ __forceinline__ void fma_8x4(float acc[32], const float* __restrict__ As,
                                        const float* __restrict__ Bs, int ty, int tx) {
#pragma unroll
    for (int k = 0; k < 16; k++) {
        float4 A0 = *(const float4*)&As[k * 128 + ty * 8];
        float4 A1 = *(const float4*)&As[k * 128 + ty * 8 + 4];
        float4 B0 = *(const float4*)&Bs[k * 64 + tx * 4];
        float a[8] = {A0.x, A0.y, A0.z, A0.w, A1.x, A1.y, A1.z, A1.w};
        float b[4] = {B0.x, B0.y, B0.z, B0.w};
#pragma unroll
        for (int i = 0; i < 8; i++)
#pragma unroll
            for (int j = 0; j < 4; j++) acc[i * 4 + j] = fmaf(a[i], b[j], acc[i * 4 + j]);
    }
}

// ---------------- K3: queue ----------------
__global__ void k3_queue(const float* __restrict__ memory) {
    __shared__ __align__(16) float As[16 * 128];
    __shared__ __align__(16) float Bs[16 * 64];
    int n = blockIdx.z;
    int q0 = blockIdx.y * 128;
    int c0 = blockIdx.x * 64;
    int tid = threadIdx.x;
    int ty = tid >> 4, tx = tid & 15;
    float acc[32];
#pragma unroll
    for (int i = 0; i < 32; i++) acc[i] = 0.f;
    const float* Abase = g_A + (size_t)n * SS * QQ + q0;
    const float* Bbase = memory + (size_t)n * CC + c0;
    for (int s0 = 0; s0 < SS; s0 += 16) {
#pragma unroll
        for (int l = 0; l < 2; l++) {
            int f = tid + l * 256;
            int row = f >> 5, col4 = f & 31;
            *(float4*)&As[row * 128 + col4 * 4] =
                *(const float4*)&Abase[(size_t)(s0 + row) * QQ + col4 * 4];
        }
        {
            int rb = tid >> 4, cb = tid & 15;
            *(float4*)&Bs[rb * 64 + cb * 4] =
                *(const float4*)&Bbase[(size_t)(s0 + rb) * NN * CC + cb * 4];
        }
        __syncthreads();
        fma_8x4(acc, As, Bs, ty, tx);
        __syncthreads();
    }
#pragma unroll
    for (int i = 0; i < 8; i++) {
        int q = q0 + ty * 8 + i;
        float4 v = make_float4(acc[i * 4], acc[i * 4 + 1], acc[i * 4 + 2], acc[i * 4 + 3]);
        *(float4*)&g_queue[((size_t)q * NN + n) * CC + c0 + tx * 4] = v;
    }
}

// ---------------- K4: xg = queue @ W_ih^T via tf32 mma.sync ----------------
__global__ void __launch_bounds__(256) k4_xgates(const float* __restrict__ W_ih,
                                                 const float* __restrict__ b_ih,
                                                 const float* __restrict__ b_hh) {
    __shared__ __align__(16) float As[128 * 20];
    __shared__ __align__(16) float Bs[128 * 20];
    int tid = threadIdx.x;
    int m0 = blockIdx.y * 128, g0 = blockIdx.x * 128;
    int warp = tid >> 5, lane = tid & 31;
    int wm = warp >> 1, wn = warp & 1;
    int lr = lane >> 2, lc = lane & 3;

    float c[2][8][4];
#pragma unroll
    for (int a = 0; a < 2; a++)
#pragma unroll
        for (int b = 0; b < 8; b++)
#pragma unroll
            for (int d = 0; d < 4; d++) c[a][b][d] = 0.f;

    int sr = tid >> 2;
    int sk = (tid & 3) * 4;
    const float* Ag = g_queue + (size_t)(m0 + sr) * CC + sk;
    const float* Bg = W_ih + (size_t)(g0 + sr) * CC + sk;

    float4 ra0 = *(const float4*)Ag;
    float4 ra1 = *(const float4*)(Ag + (size_t)64 * CC);
    float4 rb0 = *(const float4*)Bg;
    float4 rb1 = *(const float4*)(Bg + (size_t)64 * CC);

    for (int kt = 0; kt < 32; kt++) {
        *(float4*)&As[sr * 20 + sk] =
            make_float4(to_tf32(ra0.x), to_tf32(ra0.y), to_tf32(ra0.z), to_tf32(ra0.w));
        *(float4*)&As[(sr + 64) * 20 + sk] =
            make_float4(to_tf32(ra1.x), to_tf32(ra1.y), to_tf32(ra1.z), to_tf32(ra1.w));
        *(float4*)&Bs[sr * 20 + sk] =
            make_float4(to_tf32(rb0.x), to_tf32(rb0.y), to_tf32(rb0.z), to_tf32(rb0.w));
        *(float4*)&Bs[(sr + 64) * 20 + sk] =
            make_float4(to_tf32(rb1.x), to_tf32(rb1.y), to_tf32(rb1.z), to_tf32(rb1.w));
        __syncthreads();
        if (kt < 31) {
            int off = (kt + 1) * 16;
            ra0 = *(const float4*)(Ag + off);
            ra1 = *(const float4*)(Ag + (size_t)64 * CC + off);
            rb0 = *(const float4*)(Bg + off);
            rb1 = *(const float4*)(Bg + (size_t)64 * CC + off);
        }
#pragma unroll
        for (int s = 0; s < 2; s++) {
            int k0 = s * 8;
            float a[2][4];
#pragma unroll
            for (int tm = 0; tm < 2; tm++) {
                int row = wm * 32 + tm * 16 + lr;
                a[tm][0] = As[row * 20 + k0 + lc];
                a[tm][1] = As[(row + 8) * 20 + k0 + lc];
                a[tm][2] = As[row * 20 + k0 + lc + 4];
                a[tm][3] = As[(row + 8) * 20 + k0 + lc + 4];
            }
#pragma unroll
            for (int tn = 0; tn < 8; tn++) {
                int col = wn * 64 + tn * 8 + lr;
                float b0 = Bs[col * 20 + k0 + lc];
                float b1 = Bs[col * 20 + k0 + lc + 4];
#pragma unroll
                for (int tm = 0; tm < 2; tm++)
                    mma_tf32(c[tm][tn][0], c[tm][tn][1], c[tm][tn][2], c[tm][tn][3],
                             a[tm][0], a[tm][1], a[tm][2], a[tm][3], b0, b1);
            }
        }
        __syncthreads();
    }
#pragma unroll
    for (int tm = 0; tm < 2; tm++) {
#pragma unroll
        for (int tn = 0; tn < 8; tn++) {
            int g = g0 + wn * 64 + tn * 8 + lc * 2;
            float bv0 = b_ih[g] + b_hh[g];
            float bv1 = b_ih[g + 1] + b_hh[g + 1];
            int r0 = m0 + wm * 32 + tm * 16 + lr;
            float2 v0 = make_float2(c[tm][tn][0] + bv0, c[tm][tn][1] + bv1);
            float2 v1 = make_float2(c[tm][tn][2] + bv0, c[tm][tn][3] + bv1);
            *(float2*)&g_xg[(size_t)r0 * GG + g] = v0;
            *(float2*)&g_xg[(size_t)(r0 + 8) * GG + g] = v1;
        }
    }
}

// ---------------- K5: persistent LSTM (tf32 mma) ----------------
__device__ __forceinline__ float sigf(float x) { return 1.f / (1.f + expf(-x)); }

__device__ __forceinline__ void gridbar(unsigned target) {
    if (threadIdx.x == 0) {
        __threadfence();
        atomicAdd(&g_barcnt, 1u);
        while (*(volatile unsigned*)&g_barcnt < target) __nanosleep(32);
        __threadfence();
    }
    __syncthreads();
}

__global__ void __launch_bounds__(256, 1) k5_lstm(const float* __restrict__ W_hh) {
    extern __shared__ float sm[];
    float* hts = sm;                       // [64][HTS2]  (A: h as [n][k], tf32 values)
    float* wts = sm + NN * HTS2;           // [512][WTS2] (B: W as [k][gi], tf32 values)
    float* red = wts + CC * WTS2;          // [4][256]    K-half reduction
    float* gsm = red + 4 * 256;            // [16][64]    gates [gi][n]
    int tid = threadIdx.x;
    int b = blockIdx.x;
    int c0 = b * 4;
    int wid = tid >> 5, lane = tid & 31;
    int mt = wid & 3, kh = wid >> 2;       // m-tile 0..3, K-half 0..1
    int gid = lane >> 2, tig = lane & 3;

    // preload W slice as tf32 into wts[k][gi], gi = gate*4 + j
    {
        int gi = tid >> 4;                 // 0..15
        int gate = gi >> 2, j = gi & 3;
        const float* wrow = W_hh + (size_t)(gate * CC + c0 + j) * CC;
        int kc = (tid & 15) * 32;
#pragma unroll
        for (int u = 0; u < 8; u++) {
            float4 v = *(const float4*)&wrow[kc + u * 4];
            wts[(kc + u * 4 + 0) * WTS2 + gi] = to_tf32(v.x);
            wts[(kc + u * 4 + 1) * WTS2 + gi] = to_tf32(v.y);
            wts[(kc + u * 4 + 2) * WTS2 + gi] = to_tf32(v.z);
            wts[(kc + u * 4 + 3) * WTS2 + gi] = to_tf32(v.w);
        }
    }
    // zero this block's h columns (buffer 0)
    if (tid < 64) {
        *(float4*)&g_gh[tid * CC + c0] = make_float4(0.f, 0.f, 0.f, 0.f);
    }
    __syncthreads();
    unsigned u = 1;
    gridbar(u * NB5); u++;

    float creg[4] = {0.f, 0.f, 0.f, 0.f};

    for (int step = 0; step < QQ; step++) {
        int par = step & 1;
        // prefetch this step's input gates
        float xvf[4][4];
        if (tid < 64) {
            const float* xb = g_xg + ((size_t)step * NN + tid) * GG + c0;
#pragma unroll
            for (int g = 0; g < 4; g++) {
                float4 v = *(const float4*)&xb[g * 512];
                xvf[g][0] = v.x; xvf[g][1] = v.y; xvf[g][2] = v.z; xvf[g][3] = v.w;
            }
        }
        // stage h [n][k] into smem (values already tf32-rounded at write)
        const float* hb = g_gh + par * (NN * CC);
#pragma unroll
        for (int it = 0; it < 32; it++) {
            int f = tid + it * 256;        // float4 slot 0..8191
            int n = f >> 7;
            int k4 = (f & 127) * 4;
            float4 v = __ldcg((const float4*)&hb[n * CC + k4]);
            *(float4*)&hts[n * HTS2 + k4] = v;
        }
        __syncthreads();

        // tensor GEMM: gates[64n x 16gi] = h[64x512] @ Wt[512x16]
        float c[2][4];
#pragma unroll
        for (int nt = 0; nt < 2; nt++)
#pragma unroll
            for (int i = 0; i < 4; i++) c[nt][i] = 0.f;
        const float* Ab = &hts[(mt * 16) * HTS2 + kh * 256];
        const float* Bb = &wts[(kh * 256) * WTS2];
#pragma unroll
        for (int kc = 0; kc < 32; kc++) {
            int k0 = kc * 8;
            float a0 = Ab[gid * HTS2 + k0 + tig];
            float a1 = Ab[(gid + 8) * HTS2 + k0 + tig];
            float a2 = Ab[gid * HTS2 + k0 + tig + 4];
            float a3 = Ab[(gid + 8) * HTS2 + k0 + tig + 4];
#pragma unroll
            for (int nt = 0; nt < 2; nt++) {
                float b0 = Bb[(k0 + tig) * WTS2 + nt * 8 + gid];
                float b1 = Bb[(k0 + tig + 4) * WTS2 + nt * 8 + gid];
                mma_tf32(c[nt][0], c[nt][1], c[nt][2], c[nt][3],
                         a0, a1, a2, a3, b0, b1);
            }
        }
        // K-half reduction
        if (kh == 1) {
#pragma unroll
            for (int nt = 0; nt < 2; nt++) {
                *(float4*)&red[mt * 256 + nt * 128 + lane * 4] =
                    make_float4(c[nt][0], c[nt][1], c[nt][2], c[nt][3]);
            }
        }
        __syncthreads();
        if (kh == 0) {
#pragma unroll
            for (int nt = 0; nt < 2; nt++) {
                float4 r = *(const float4*)&red[mt * 256 + nt * 128 + lane * 4];
                c[nt][0] += r.x; c[nt][1] += r.y; c[nt][2] += r.z; c[nt][3] += r.w;
                int n0 = mt * 16 + gid;
                int gi0 = nt * 8 + tig * 2;
                gsm[gi0 * 64 + n0] = c[nt][0];
                gsm[(gi0 + 1) * 64 + n0] = c[nt][1];
                gsm[gi0 * 64 + n0 + 8] = c[nt][2];
                gsm[(gi0 + 1) * 64 + n0 + 8] = c[nt][3];
            }
        }
        __syncthreads();

        // activation + h/c update
        if (tid < 64) {
            int nxt = (step + 1) & 1;
            float* ho = g_gh + nxt * (NN * CC) + tid * CC + c0;
            float* hsout = g_hs + ((size_t)step * NN + tid) * CC + c0;
#pragma unroll
            for (int j = 0; j < 4; j++) {
                float iv = gsm[(0 * 4 + j) * 64 + tid] + xvf[0][j];
                float fv = gsm[(1 * 4 + j) * 64 + tid] + xvf[1][j];
                float gv = gsm[(2 * 4 + j) * 64 + tid] + xvf[2][j];
                float ov = gsm[(3 * 4 + j) * 64 + tid] + xvf[3][j];
                float cc = sigf(fv) * creg[j] + sigf(iv) * tanhf(gv);
                creg[j] = cc;
                float h = sigf(ov) * tanhf(cc);
                ho[j] = to_tf32(h);        // recurrence path: tf32-rounded
                hsout[j] = h;              // LN path: full precision
            }
        }
        __syncthreads();
        gridbar(u * NB5); u++;
    }
}

// ---------------- K6: LayerNorm + decode ----------------
__global__ void k6_lndec(const float* __restrict__ gamma,
                         const float* __restrict__ beta,
                         const float* __restrict__ W_dec,
                         const float* __restrict__ b_dec,
                         float* __restrict__ out) {
    __shared__ float sW[CC * VV];
    __shared__ float sG[CC], sB[CC], sbd[VV];
    int tid = threadIdx.x;
    for (int i = tid; i < CC * VV; i += 256) sW[i] = W_dec[i];
    for (int i = tid; i < CC; i += 256) { sG[i] = gamma[i]; sB[i] = beta[i]; }
    if (tid < VV) sbd[tid] = b_dec[tid];
    __syncthreads();

    int warp = blockIdx.x * 8 + (tid >> 5);
    int lane = tid & 31;
    if (warp >= QQ * NN) return;
    const float* row = g_hs + (size_t)warp * CC;

    float x[16];
    float s = 0.f, s2 = 0.f;
#pragma unroll
    for (int t = 0; t < 4; t++) {
        float4 v = *(const float4*)&row[lane * 4 + t * 128];
        x[t * 4 + 0] = v.x; x[t * 4 + 1] = v.y; x[t * 4 + 2] = v.z; x[t * 4 + 3] = v.w;
        s += v.x + v.y + v.z + v.w;
        s2 += v.x * v.x + v.y * v.y + v.z * v.z + v.w * v.w;
    }
#pragma unroll
    for (int o = 16; o; o >>= 1) {
        s += __shfl_xor_sync(0xffffffffu, s, o);
        s2 += __shfl_xor_sync(0xffffffffu, s2, o);
    }
    float mu = s * (1.f / CC);
    float var = s2 * (1.f / CC) - mu * mu;
    float rs = rsqrtf(var + 1e-5f);

    float acc[VV];
#pragma unroll
    for (int v = 0; v < VV; v++) acc[v] = 0.f;
#pragma unroll
    for (int t = 0; t < 4; t++) {
#pragma unroll
        for (int e = 0; e < 4; e++) {
            int c = lane * 4 + t * 128 + e;
            float nv = (x[t * 4 + e] - mu) * rs * sG[c] + sB[c];
#pragma unroll
            for (int v = 0; v < VV; v++) acc[v] = fmaf(nv, sW[c * VV + v], acc[v]);
        }
    }
#pragma unroll
    for (int v = 0; v < VV; v++) {
        float a = acc[v];
#pragma unroll
        for (int o = 16; o; o >>= 1) a += __shfl_xor_sync(0xffffffffu, a, o);
        if (lane == 0) out[(size_t)warp * VV + v] = a + sbd[v];
    }
}

extern "C" void kernel_launch(void* const* d_in, const int* in_sizes, int n_in,
                              void* d_out, int out_size) {
    const float* memory = (const float*)d_in[0];
    const float* W_act  = (const float*)d_in[1];
    const float* b_act  = (const float*)d_in[2];
    const float* W_ih   = (const float*)d_in[3];
    const float* W_hh   = (const float*)d_in[4];
    const float* b_ih   = (const float*)d_in[5];
    const float* b_hh   = (const float*)d_in[6];
    const float* lng    = (const float*)d_in[7];
    const float* lnb    = (const float*)d_in[8];
    const float* W_dec  = (const float*)d_in[9];
    const float* b_dec  = (const float*)d_in[10];
    float* out = (float*)d_out;

    k1_actions<<<(SS * NN + 7) / 8, 256>>>(memory, W_act, b_act);
    k2_posvec<<<NN, QQ>>>();
    k3_queue<<<dim3(CC / 64, QQ / 128, NN), 256>>>(memory);
    k4_xgates<<<dim3(GG / 128, (QQ * NN) / 128), 256>>>(W_ih, b_ih, b_hh);

    int smem5 = (NN * HTS2 + CC * WTS2 + 4 * 256 + 16 * 64) * sizeof(float);
    cudaFuncSetAttribute(k5_lstm, cudaFuncAttributeMaxDynamicSharedMemorySize, smem5);
    k5_lstm<<<NB5, 256, smem5>>>(W_hh);

    k6_lndec<<<(QQ * NN + 7) / 8, 256>>>(lng, lnb, W_dec, b_dec, out);
}